// round 11
// baseline (speedup 1.0000x reference)
#include <cuda_runtime.h>
#include <cuda_bf16.h>
#include <cuda_fp16.h>
#include <math.h>

#define BATCH 128
#define HW 224
#define CH 3
#define KK 32
#define PAD_LO 15                       // SAME pad for K=32: lo=15, hi=16
#define ROW_FLOATS (HW * CH)            // 672
#define ELEMS_PER_IMG (HW * HW * CH)    // 150528
#define MAX_TAPS 64

#define RB 16                           // output rows per block
#define SROWS (RB + 31)                 // staged rows = 47
#define SPPX 256                        // staged row width in px (16+224+16)
#define NTHREADS 896                    // 4 row-groups x 224 px
#define ROW_F4 168                      // float4 per source row (672/4)

__device__ int   g_cnt[BATCH];
__device__ float g_w[BATCH];            // uniform nonzero weight = 1/size
__device__ int   g_off[BATCH][MAX_TAPS];  // tap offset: dy*SPPX + dx (px units)

__device__ __forceinline__ __half2 u32_to_h2(unsigned u) {
    union { unsigned u; __half2 h; } cv; cv.u = u; return cv.h;
}

// ---------------------------------------------------------------------------
// Kernel 1: build rotated sparse tap list. One block per sample, one thread
// per kernel cell. Compaction order irrelevant (all nonzero weights equal).
// ---------------------------------------------------------------------------
__global__ void build_taps_kernel(const float* __restrict__ tbl,
                                  const int* __restrict__ amt,
                                  const int* __restrict__ angles) {
    const int b = blockIdx.x;
    const int tid = threadIdx.x;           // 0..1023
    const int yy = tid >> 5;
    const int xx = tid & 31;

    __shared__ int s_cnt;
    if (tid == 0) s_cnt = 0;
    __syncthreads();

    float rad = (float)angles[b] * 0.017453292519943295f;
    float c = cosf(rad);
    float s = sinf(rad);
    const float e = 31.0f;
    float x_off = (e - (c * e - s * e)) * 0.5f;
    float y_off = (e - (s * e + c * e)) * 0.5f;

    float sx = c * (float)xx - s * (float)yy + x_off;
    float sy = s * (float)xx + c * (float)yy + y_off;
    int ix = __float2int_rn(sx);           // round half to even == jnp.round
    int iy = __float2int_rn(sy);

    if (ix >= 0 && ix < KK && iy >= 0 && iy < KK) {
        // reference indexes kernels_table[amt] directly
        float w = tbl[((size_t)amt[b] * (KK * KK) + iy * KK + ix) * CH];
        if (w != 0.0f) {
            int dy = yy - PAD_LO;
            int dx = xx - PAD_LO;
            int k = atomicAdd(&s_cnt, 1);
            g_off[b][k] = dy * SPPX + dx;  // px-unit offset in staged tile
            g_w[b] = w;                    // all equal; benign race
        }
    }
    __syncthreads();
    if (tid == 0) g_cnt[b] = s_cnt;
}

// ---------------------------------------------------------------------------
// Kernel 2 (fused): stage halo'd fp16-RGBX window in SMEM via float4
// coalesced loads, then sparse conv from SMEM. Block = 16 output rows,
// thread = 1 px x 4 rows (rg, rg+4, rg+8, rg+12).
// ---------------------------------------------------------------------------
__global__ void __launch_bounds__(NTHREADS, 2)
blur_fused_kernel(const float* __restrict__ in, float* __restrict__ out) {
    extern __shared__ char sm[];
    int*    s_off = (int*)sm;                      // 256 B
    uint2*  tile  = (uint2*)(sm + 1024);           // SROWS*SPPX*8 = 96256 B
    __half* tileh = (__half*)tile;                 // 4 halves per px

    const int b   = blockIdx.y;
    const int yb  = blockIdx.x * RB;
    const int tid = threadIdx.x;
    const int cnt = g_cnt[b];

    if (tid < cnt) s_off[tid] = g_off[b][tid];

    // ---- zero-fill tile (wide stores) ----
    {
        uint4 z = make_uint4(0u, 0u, 0u, 0u);
        uint4* t4 = (uint4*)tile;
        for (int i = tid; i < SROWS * SPPX / 2; i += NTHREADS) t4[i] = z;
    }
    __syncthreads();

    // ---- stage: coalesced float4 loads, scatter halves into RGBX tile ----
    const float* img = in + (size_t)b * ELEMS_PER_IMG;
    for (int i = tid; i < SROWS * ROW_F4; i += NTHREADS) {
        int row = i / ROW_F4;              // 0..46
        int j   = i - row * ROW_F4;        // float4 within row, 0..167
        int ys  = yb + row - 15;
        if ((unsigned)ys < (unsigned)HW) {
            float4 v = __ldg((const float4*)(img + ys * ROW_FLOATS) + j);
            int f = 4 * j;                 // float index within row
            __half* dst = tileh + row * (SPPX * 4) + 64;  // x-halo: +16 px = 64 halves
            // half slot = px*4 + ch, px = f/3, ch = f%3
            dst[(f    ) / 3 * 4 + (f    ) % 3] = __float2half_rn(v.x);
            dst[(f + 1) / 3 * 4 + (f + 1) % 3] = __float2half_rn(v.y);
            dst[(f + 2) / 3 * 4 + (f + 2) % 3] = __float2half_rn(v.z);
            dst[(f + 3) / 3 * 4 + (f + 3) % 3] = __float2half_rn(v.w);
        }
    }
    __syncthreads();

    // ---- conv: thread = px x, rows yb+rg+{0,4,8,12} ----
    const int x  = tid % HW;               // 0..223
    const int rg = tid / HW;               // 0..3

    const uint2* tp = tile + (15 + rg) * SPPX + (16 + x);

    float a0 = 0.f, a1 = 0.f, a2 = 0.f;
    float b0 = 0.f, b1 = 0.f, b2 = 0.f;
    float c0 = 0.f, c1 = 0.f, c2 = 0.f;
    float d0 = 0.f, d1 = 0.f, d2 = 0.f;
    #pragma unroll 2
    for (int i = 0; i < cnt; i++) {
        int off = s_off[i];
        uint2 v0 = tp[off];
        uint2 v1 = tp[off +  4 * SPPX];
        uint2 v2 = tp[off +  8 * SPPX];
        uint2 v3 = tp[off + 12 * SPPX];
        float2 f0 = __half22float2(u32_to_h2(v0.x));
        float2 f1 = __half22float2(u32_to_h2(v1.x));
        float2 f2 = __half22float2(u32_to_h2(v2.x));
        float2 f3 = __half22float2(u32_to_h2(v3.x));
        a0 += f0.x; a1 += f0.y; a2 += __half2float(__low2half(u32_to_h2(v0.y)));
        b0 += f1.x; b1 += f1.y; b2 += __half2float(__low2half(u32_to_h2(v1.y)));
        c0 += f2.x; c1 += f2.y; c2 += __half2float(__low2half(u32_to_h2(v2.y)));
        d0 += f3.x; d1 += f3.y; d2 += __half2float(__low2half(u32_to_h2(v3.y)));
    }

    const float w = g_w[b];
    float* o = out + (size_t)b * ELEMS_PER_IMG + (size_t)(yb + rg) * ROW_FLOATS + x * CH;
    o[0] = w * a0;  o[1] = w * a1;  o[2] = w * a2;
    o += 4 * ROW_FLOATS;
    o[0] = w * b0;  o[1] = w * b1;  o[2] = w * b2;
    o += 4 * ROW_FLOATS;
    o[0] = w * c0;  o[1] = w * c1;  o[2] = w * c2;
    o += 4 * ROW_FLOATS;
    o[0] = w * d0;  o[1] = w * d1;  o[2] = w * d2;
}

// ---------------------------------------------------------------------------
// Inputs (metadata order): x f32[128,224,224,3], kernels_table f32[32,32,32,3],
//                          amt i32[128], angles i32[128]
// ---------------------------------------------------------------------------
extern "C" void kernel_launch(void* const* d_in, const int* in_sizes, int n_in,
                              void* d_out, int out_size) {
    const float* x      = (const float*)d_in[0];
    const float* tbl    = (const float*)d_in[1];
    const int*   amt    = (const int*)d_in[2];
    const int*   angles = (const int*)d_in[3];
    float*       out    = (float*)d_out;

    static int smem_set = 0;
    const int smem_bytes = 1024 + SROWS * SPPX * 8;   // 97280
    if (!smem_set) {
        cudaFuncSetAttribute(blur_fused_kernel,
                             cudaFuncAttributeMaxDynamicSharedMemorySize, smem_bytes);
        smem_set = 1;
    }

    build_taps_kernel<<<BATCH, KK * KK>>>(tbl, amt, angles);

    dim3 cgrid(HW / RB, BATCH);            // 14 x 128
    blur_fused_kernel<<<cgrid, NTHREADS, smem_bytes>>>(x, out);
}

// round 12
// speedup vs baseline: 1.2831x; 1.2831x over previous
#include <cuda_runtime.h>
#include <cuda_bf16.h>
#include <cuda_fp16.h>
#include <math.h>

#define BATCH 128
#define HW 224
#define CH 3
#define KK 32
#define PAD_LO 15                       // SAME pad for K=32: lo=15, hi=16
#define ROW_FLOATS (HW * CH)            // 672
#define ELEMS_PER_IMG (HW * HW * CH)    // 150528
#define MAX_TAPS 64

#define RB 16                           // output rows per block
#define SROWS (RB + 31)                 // staged rows = 47
#define SPPX 256                        // staged row width in px (16+224+16)
#define NTHREADS 896                    // 4 row-groups x 224 px

__device__ int   g_cnt[BATCH];
__device__ float g_w[BATCH];            // uniform nonzero weight = 1/size
__device__ int   g_off[BATCH][MAX_TAPS];  // tap offset: dy*SPPX + dx (px units)

__device__ __forceinline__ unsigned h2_to_u32(__half2 h) {
    union { __half2 h; unsigned u; } cv; cv.h = h; return cv.u;
}
__device__ __forceinline__ __half2 u32_to_h2(unsigned u) {
    union { unsigned u; __half2 h; } cv; cv.u = u; return cv.h;
}

// ---------------------------------------------------------------------------
// Kernel 1: build rotated sparse tap list. One block per sample, one thread
// per kernel cell. Compaction order irrelevant (all nonzero weights equal).
// ---------------------------------------------------------------------------
__global__ void build_taps_kernel(const float* __restrict__ tbl,
                                  const int* __restrict__ amt,
                                  const int* __restrict__ angles) {
    const int b = blockIdx.x;
    const int tid = threadIdx.x;           // 0..1023
    const int yy = tid >> 5;
    const int xx = tid & 31;

    __shared__ int s_cnt;
    if (tid == 0) s_cnt = 0;
    __syncthreads();

    float rad = (float)angles[b] * 0.017453292519943295f;
    float c = cosf(rad);
    float s = sinf(rad);
    const float e = 31.0f;
    float x_off = (e - (c * e - s * e)) * 0.5f;
    float y_off = (e - (s * e + c * e)) * 0.5f;

    float sx = c * (float)xx - s * (float)yy + x_off;
    float sy = s * (float)xx + c * (float)yy + y_off;
    int ix = __float2int_rn(sx);           // round half to even == jnp.round
    int iy = __float2int_rn(sy);

    if (ix >= 0 && ix < KK && iy >= 0 && iy < KK) {
        // reference indexes kernels_table[amt] directly
        float w = tbl[((size_t)amt[b] * (KK * KK) + iy * KK + ix) * CH];
        if (w != 0.0f) {
            int dy = yy - PAD_LO;
            int dx = xx - PAD_LO;
            int k = atomicAdd(&s_cnt, 1);
            g_off[b][k] = dy * SPPX + dx;  // px-unit offset in staged tile
            g_w[b] = w;                    // all equal; benign race
        }
    }
    __syncthreads();
    if (tid == 0) g_cnt[b] = s_cnt;
}

// ---------------------------------------------------------------------------
// Kernel 2 (fused): stage halo'd fp16-RGBX window in SMEM (cheap scalar
// per-px staging, as in R10), then sparse conv from SMEM.
// Block = 16 output rows; thread = 1 px x 4 rows (rg, rg+4, rg+8, rg+12).
// ---------------------------------------------------------------------------
__global__ void __launch_bounds__(NTHREADS, 2)
blur_fused_kernel(const float* __restrict__ in, float* __restrict__ out) {
    extern __shared__ char sm[];
    int*   s_off = (int*)sm;                       // 256 B
    uint2* tile  = (uint2*)(sm + 1024);            // SROWS*SPPX*8 = 96256 B

    const int b   = blockIdx.y;
    const int yb  = blockIdx.x * RB;
    const int tid = threadIdx.x;
    const int cnt = g_cnt[b];

    if (tid < cnt) s_off[tid] = g_off[b][tid];

    // ---- stage: rows [yb-15, yb+31], x in [-16, 240) -> half4 RGBX ----
    const float* img = in + (size_t)b * ELEMS_PER_IMG;
    for (int i = tid; i < SROWS * SPPX; i += NTHREADS) {
        int row = i >> 8;                  // 0..46
        int px  = i & 255;                 // 0..255
        int ys  = yb + row - 15;
        int xs  = px - 16;
        uint2 v = make_uint2(0u, 0u);
        if ((unsigned)ys < (unsigned)HW && (unsigned)xs < (unsigned)HW) {
            const float* p = img + ys * ROW_FLOATS + xs * CH;
            v.x = h2_to_u32(__floats2half2_rn(__ldg(p), __ldg(p + 1)));
            v.y = h2_to_u32(__floats2half2_rn(__ldg(p + 2), 0.f));
        }
        tile[i] = v;
    }
    __syncthreads();

    // ---- conv: thread = px x, rows yb+rg+{0,4,8,12} ----
    const int x  = tid % HW;               // 0..223
    const int rg = tid / HW;               // 0..3

    const uint2* tp = tile + (15 + rg) * SPPX + (16 + x);

    float a0 = 0.f, a1 = 0.f, a2 = 0.f;
    float b0 = 0.f, b1 = 0.f, b2 = 0.f;
    float c0 = 0.f, c1 = 0.f, c2 = 0.f;
    float d0 = 0.f, d1 = 0.f, d2 = 0.f;
    #pragma unroll 2
    for (int i = 0; i < cnt; i++) {
        int off = s_off[i];
        uint2 v0 = tp[off];
        uint2 v1 = tp[off +  4 * SPPX];
        uint2 v2 = tp[off +  8 * SPPX];
        uint2 v3 = tp[off + 12 * SPPX];
        float2 f0 = __half22float2(u32_to_h2(v0.x));
        float2 f1 = __half22float2(u32_to_h2(v1.x));
        float2 f2 = __half22float2(u32_to_h2(v2.x));
        float2 f3 = __half22float2(u32_to_h2(v3.x));
        a0 += f0.x; a1 += f0.y; a2 += __half2float(__low2half(u32_to_h2(v0.y)));
        b0 += f1.x; b1 += f1.y; b2 += __half2float(__low2half(u32_to_h2(v1.y)));
        c0 += f2.x; c1 += f2.y; c2 += __half2float(__low2half(u32_to_h2(v2.y)));
        d0 += f3.x; d1 += f3.y; d2 += __half2float(__low2half(u32_to_h2(v3.y)));
    }

    const float w = g_w[b];
    float* o = out + (size_t)b * ELEMS_PER_IMG + (size_t)(yb + rg) * ROW_FLOATS + x * CH;
    o[0] = w * a0;  o[1] = w * a1;  o[2] = w * a2;
    o += 4 * ROW_FLOATS;
    o[0] = w * b0;  o[1] = w * b1;  o[2] = w * b2;
    o += 4 * ROW_FLOATS;
    o[0] = w * c0;  o[1] = w * c1;  o[2] = w * c2;
    o += 4 * ROW_FLOATS;
    o[0] = w * d0;  o[1] = w * d1;  o[2] = w * d2;
}

// ---------------------------------------------------------------------------
// Inputs (metadata order): x f32[128,224,224,3], kernels_table f32[32,32,32,3],
//                          amt i32[128], angles i32[128]
// ---------------------------------------------------------------------------
extern "C" void kernel_launch(void* const* d_in, const int* in_sizes, int n_in,
                              void* d_out, int out_size) {
    const float* x      = (const float*)d_in[0];
    const float* tbl    = (const float*)d_in[1];
    const int*   amt    = (const int*)d_in[2];
    const int*   angles = (const int*)d_in[3];
    float*       out    = (float*)d_out;

    static int smem_set = 0;
    const int smem_bytes = 1024 + SROWS * SPPX * 8;   // 97280
    if (!smem_set) {
        cudaFuncSetAttribute(blur_fused_kernel,
                             cudaFuncAttributeMaxDynamicSharedMemorySize, smem_bytes);
        smem_set = 1;
    }

    build_taps_kernel<<<BATCH, KK * KK>>>(tbl, amt, angles);

    dim3 cgrid(HW / RB, BATCH);            // 14 x 128
    blur_fused_kernel<<<cgrid, NTHREADS, smem_bytes>>>(x, out);
}

// round 13
// speedup vs baseline: 1.5935x; 1.2419x over previous
#include <cuda_runtime.h>
#include <cuda_bf16.h>
#include <cuda_fp16.h>
#include <math.h>

#define BATCH 128
#define HW 224
#define CH 3
#define KK 32
#define PAD_LO 15                       // SAME pad for K=32: lo=15, hi=16
#define ROW_FLOATS (HW * CH)            // 672
#define ELEMS_PER_IMG (HW * HW * CH)    // 150528
#define MAX_TAPS 64

#define RB 16                           // output rows per block
#define XB 112                          // output cols per block
#define SROWS (RB + 31)                 // staged rows = 47
#define SPPX (XB + 32)                  // staged row width = 144 px
#define STOT (SROWS * SPPX)             // 6768 staged px
#define NTHREADS 448                    // 4 row-groups x 112 px

__device__ int   g_cnt[BATCH];
__device__ float g_w[BATCH];            // uniform nonzero weight = 1/size
__device__ int   g_off[BATCH][MAX_TAPS];  // tap offset: dy*SPPX + dx (px units)

__device__ __forceinline__ unsigned h2_to_u32(__half2 h) {
    union { __half2 h; unsigned u; } cv; cv.h = h; return cv.u;
}
__device__ __forceinline__ __half2 u32_to_h2(unsigned u) {
    union { unsigned u; __half2 h; } cv; cv.u = u; return cv.h;
}

// ---------------------------------------------------------------------------
// Kernel 1: build rotated sparse tap list. One block per sample, one thread
// per kernel cell. Compaction order irrelevant (all nonzero weights equal).
// ---------------------------------------------------------------------------
__global__ void build_taps_kernel(const float* __restrict__ tbl,
                                  const int* __restrict__ amt,
                                  const int* __restrict__ angles) {
    const int b = blockIdx.x;
    const int tid = threadIdx.x;           // 0..1023
    const int yy = tid >> 5;
    const int xx = tid & 31;

    __shared__ int s_cnt;
    if (tid == 0) s_cnt = 0;
    __syncthreads();

    float rad = (float)angles[b] * 0.017453292519943295f;
    float c = cosf(rad);
    float s = sinf(rad);
    const float e = 31.0f;
    float x_off = (e - (c * e - s * e)) * 0.5f;
    float y_off = (e - (s * e + c * e)) * 0.5f;

    float sx = c * (float)xx - s * (float)yy + x_off;
    float sy = s * (float)xx + c * (float)yy + y_off;
    int ix = __float2int_rn(sx);           // round half to even == jnp.round
    int iy = __float2int_rn(sy);

    if (ix >= 0 && ix < KK && iy >= 0 && iy < KK) {
        // reference indexes kernels_table[amt] directly
        float w = tbl[((size_t)amt[b] * (KK * KK) + iy * KK + ix) * CH];
        if (w != 0.0f) {
            int dy = yy - PAD_LO;
            int dx = xx - PAD_LO;
            int k = atomicAdd(&s_cnt, 1);
            g_off[b][k] = dy * SPPX + dx;  // px-unit offset in staged tile
            g_w[b] = w;                    // all equal; benign race
        }
    }
    __syncthreads();
    if (tid == 0) g_cnt[b] = s_cnt;
}

// ---------------------------------------------------------------------------
// Kernel 2 (fused): stage halo'd fp16-RGBX window (47 x 144 px) in SMEM with
// 4-way batched loads (high MLP), then sparse conv from SMEM.
// Block = 16 rows x 112 cols; thread = 1 px x 4 rows (rg, rg+4, rg+8, rg+12).
// 4 blocks co-resident per SM for stage/conv phase overlap.
// ---------------------------------------------------------------------------
__global__ void __launch_bounds__(NTHREADS, 4)
blur_fused_kernel(const float* __restrict__ in, float* __restrict__ out) {
    extern __shared__ char sm[];
    int*   s_off = (int*)sm;                       // 256 B
    uint2* tile  = (uint2*)(sm + 256);             // STOT*8 = 54144 B

    const int xb  = blockIdx.x * XB;               // 0 or 112
    const int yb  = blockIdx.y * RB;
    const int b   = blockIdx.z;
    const int tid = threadIdx.x;
    const int cnt = g_cnt[b];

    if (tid < cnt) s_off[tid] = g_off[b][tid];

    // ---- stage: 4-way batched (16 iterations total = 4 batches of 4) ----
    const float* img = in + (size_t)b * ELEMS_PER_IMG;
    #pragma unroll
    for (int batch = 0; batch < 4; batch++) {
        uint2 v[4];
        int   idx[4];
        #pragma unroll
        for (int k = 0; k < 4; k++) {
            int i = tid + (batch * 4 + k) * NTHREADS;
            idx[k] = i;
            v[k] = make_uint2(0u, 0u);
            if (i < STOT) {
                int row = i / SPPX;
                int px  = i - row * SPPX;
                int ys  = yb + row - 15;
                int xs  = xb + px - 16;
                if ((unsigned)ys < (unsigned)HW && (unsigned)xs < (unsigned)HW) {
                    const float* p = img + ys * ROW_FLOATS + xs * CH;
                    v[k].x = h2_to_u32(__floats2half2_rn(__ldg(p), __ldg(p + 1)));
                    v[k].y = h2_to_u32(__floats2half2_rn(__ldg(p + 2), 0.f));
                }
            }
        }
        #pragma unroll
        for (int k = 0; k < 4; k++)
            if (idx[k] < STOT) tile[idx[k]] = v[k];
    }
    __syncthreads();

    // ---- conv: thread = px x_local, rows yb+rg+{0,4,8,12} ----
    const int rg = tid / XB;               // 0..3
    const int xl = tid - rg * XB;          // 0..111

    const uint2* tp = tile + (15 + rg) * SPPX + (16 + xl);

    float a0 = 0.f, a1 = 0.f, a2 = 0.f;
    float b0 = 0.f, b1 = 0.f, b2 = 0.f;
    float c0 = 0.f, c1 = 0.f, c2 = 0.f;
    float d0 = 0.f, d1 = 0.f, d2 = 0.f;
    #pragma unroll 2
    for (int i = 0; i < cnt; i++) {
        int off = s_off[i];
        uint2 v0 = tp[off];
        uint2 v1 = tp[off +  4 * SPPX];
        uint2 v2 = tp[off +  8 * SPPX];
        uint2 v3 = tp[off + 12 * SPPX];
        float2 f0 = __half22float2(u32_to_h2(v0.x));
        float2 f1 = __half22float2(u32_to_h2(v1.x));
        float2 f2 = __half22float2(u32_to_h2(v2.x));
        float2 f3 = __half22float2(u32_to_h2(v3.x));
        a0 += f0.x; a1 += f0.y; a2 += __half2float(__low2half(u32_to_h2(v0.y)));
        b0 += f1.x; b1 += f1.y; b2 += __half2float(__low2half(u32_to_h2(v1.y)));
        c0 += f2.x; c1 += f2.y; c2 += __half2float(__low2half(u32_to_h2(v2.y)));
        d0 += f3.x; d1 += f3.y; d2 += __half2float(__low2half(u32_to_h2(v3.y)));
    }

    const float w = g_w[b];
    float* o = out + (size_t)b * ELEMS_PER_IMG
             + (size_t)(yb + rg) * ROW_FLOATS + (xb + xl) * CH;
    o[0] = w * a0;  o[1] = w * a1;  o[2] = w * a2;
    o += 4 * ROW_FLOATS;
    o[0] = w * b0;  o[1] = w * b1;  o[2] = w * b2;
    o += 4 * ROW_FLOATS;
    o[0] = w * c0;  o[1] = w * c1;  o[2] = w * c2;
    o += 4 * ROW_FLOATS;
    o[0] = w * d0;  o[1] = w * d1;  o[2] = w * d2;
}

// ---------------------------------------------------------------------------
// Inputs (metadata order): x f32[128,224,224,3], kernels_table f32[32,32,32,3],
//                          amt i32[128], angles i32[128]
// ---------------------------------------------------------------------------
extern "C" void kernel_launch(void* const* d_in, const int* in_sizes, int n_in,
                              void* d_out, int out_size) {
    const float* x      = (const float*)d_in[0];
    const float* tbl    = (const float*)d_in[1];
    const int*   amt    = (const int*)d_in[2];
    const int*   angles = (const int*)d_in[3];
    float*       out    = (float*)d_out;

    static int smem_set = 0;
    const int smem_bytes = 256 + STOT * 8;         // 54400
    if (!smem_set) {
        cudaFuncSetAttribute(blur_fused_kernel,
                             cudaFuncAttributeMaxDynamicSharedMemorySize, smem_bytes);
        smem_set = 1;
    }

    build_taps_kernel<<<BATCH, KK * KK>>>(tbl, amt, angles);

    dim3 cgrid(HW / XB, HW / RB, BATCH);   // 2 x 14 x 128
    blur_fused_kernel<<<cgrid, NTHREADS, smem_bytes>>>(x, out);
}

// round 14
// speedup vs baseline: 1.6899x; 1.0605x over previous
#include <cuda_runtime.h>
#include <cuda_bf16.h>
#include <cuda_fp16.h>
#include <math.h>

#define BATCH 128
#define HW 224
#define CH 3
#define KK 32
#define PAD_LO 15                       // SAME pad for K=32: lo=15, hi=16
#define ROW_FLOATS (HW * CH)            // 672
#define ELEMS_PER_IMG (HW * HW * CH)    // 150528
#define MAX_TAPS 64

#define RB 32                           // output rows per block
#define XB 112                          // output cols per block
#define SROWS (RB + 31)                 // staged rows = 63
#define SPPX (XB + 32)                  // staged row width = 144 px
#define STOT (SROWS * SPPX)             // 9072 staged px
#define NTHREADS 448                    // 4 row-groups x 112 px
#define NROW 8                          // rows accumulated per thread

__device__ int   g_cnt[BATCH];
__device__ float g_w[BATCH];            // uniform nonzero weight = 1/size
__device__ int   g_off[BATCH][MAX_TAPS];  // tap offset: dy*SPPX + dx (px units)

__device__ __forceinline__ unsigned h2_to_u32(__half2 h) {
    union { __half2 h; unsigned u; } cv; cv.h = h; return cv.u;
}
__device__ __forceinline__ __half2 u32_to_h2(unsigned u) {
    union { unsigned u; __half2 h; } cv; cv.u = u; return cv.h;
}

// ---------------------------------------------------------------------------
// Kernel 1: build rotated sparse tap list. One block per sample, one thread
// per kernel cell. Compaction order irrelevant (all nonzero weights equal).
// ---------------------------------------------------------------------------
__global__ void build_taps_kernel(const float* __restrict__ tbl,
                                  const int* __restrict__ amt,
                                  const int* __restrict__ angles) {
    const int b = blockIdx.x;
    const int tid = threadIdx.x;           // 0..1023
    const int yy = tid >> 5;
    const int xx = tid & 31;

    __shared__ int s_cnt;
    if (tid == 0) s_cnt = 0;
    __syncthreads();

    float rad = (float)angles[b] * 0.017453292519943295f;
    float c = cosf(rad);
    float s = sinf(rad);
    const float e = 31.0f;
    float x_off = (e - (c * e - s * e)) * 0.5f;
    float y_off = (e - (s * e + c * e)) * 0.5f;

    float sx = c * (float)xx - s * (float)yy + x_off;
    float sy = s * (float)xx + c * (float)yy + y_off;
    int ix = __float2int_rn(sx);           // round half to even == jnp.round
    int iy = __float2int_rn(sy);

    if (ix >= 0 && ix < KK && iy >= 0 && iy < KK) {
        // reference indexes kernels_table[amt] directly
        float w = tbl[((size_t)amt[b] * (KK * KK) + iy * KK + ix) * CH];
        if (w != 0.0f) {
            int dy = yy - PAD_LO;
            int dx = xx - PAD_LO;
            int k = atomicAdd(&s_cnt, 1);
            g_off[b][k] = dy * SPPX + dx;  // px-unit offset in staged tile
            g_w[b] = w;                    // all equal; benign race
        }
    }
    __syncthreads();
    if (tid == 0) g_cnt[b] = s_cnt;
}

// ---------------------------------------------------------------------------
// Kernel 2 (fused): stage halo'd fp16-RGBX window (63 x 144 px) in SMEM with
// 4-way batched loads, then sparse conv from SMEM.
// Block = 32 rows x 112 cols; thread = 1 px x 8 rows (rg+0,4,...,28).
// 3 blocks co-resident per SM.
// ---------------------------------------------------------------------------
__global__ void __launch_bounds__(NTHREADS, 3)
blur_fused_kernel(const float* __restrict__ in, float* __restrict__ out) {
    extern __shared__ char sm[];
    int*   s_off = (int*)sm;                       // 256 B
    uint2* tile  = (uint2*)(sm + 256);             // STOT*8 = 72576 B

    const int xb  = blockIdx.x * XB;               // 0 or 112
    const int yb  = blockIdx.y * RB;
    const int b   = blockIdx.z;
    const int tid = threadIdx.x;
    const int cnt = g_cnt[b];

    if (tid < cnt) s_off[tid] = g_off[b][tid];

    // ---- stage: batched loads (high MLP) ----
    const float* img = in + (size_t)b * ELEMS_PER_IMG;
    #pragma unroll
    for (int batch = 0; batch < 6; batch++) {      // 6*4*448 = 10752 >= 9072
        uint2 v[4];
        int   idx[4];
        #pragma unroll
        for (int k = 0; k < 4; k++) {
            int i = tid + (batch * 4 + k) * NTHREADS;
            idx[k] = i;
            v[k] = make_uint2(0u, 0u);
            if (i < STOT) {
                int row = i / SPPX;
                int px  = i - row * SPPX;
                int ys  = yb + row - 15;
                int xs  = xb + px - 16;
                if ((unsigned)ys < (unsigned)HW && (unsigned)xs < (unsigned)HW) {
                    const float* p = img + ys * ROW_FLOATS + xs * CH;
                    v[k].x = h2_to_u32(__floats2half2_rn(__ldg(p), __ldg(p + 1)));
                    v[k].y = h2_to_u32(__floats2half2_rn(__ldg(p + 2), 0.f));
                }
            }
        }
        #pragma unroll
        for (int k = 0; k < 4; k++)
            if (idx[k] < STOT) tile[idx[k]] = v[k];
    }
    __syncthreads();

    // ---- conv: thread = px x_local, rows yb+rg+{0,4,...,28} ----
    const int rg = tid / XB;               // 0..3
    const int xl = tid - rg * XB;          // 0..111

    const uint2* tp = tile + (15 + rg) * SPPX + (16 + xl);

    float acc[NROW][3];
    #pragma unroll
    for (int r = 0; r < NROW; r++) { acc[r][0] = 0.f; acc[r][1] = 0.f; acc[r][2] = 0.f; }

    for (int i = 0; i < cnt; i++) {
        int off = s_off[i];
        #pragma unroll
        for (int r = 0; r < NROW; r++) {
            uint2 v = tp[off + r * 4 * SPPX];
            float2 f = __half22float2(u32_to_h2(v.x));
            acc[r][0] += f.x;
            acc[r][1] += f.y;
            acc[r][2] += __half2float(__low2half(u32_to_h2(v.y)));
        }
    }

    const float w = g_w[b];
    float* o = out + (size_t)b * ELEMS_PER_IMG
             + (size_t)(yb + rg) * ROW_FLOATS + (xb + xl) * CH;
    #pragma unroll
    for (int r = 0; r < NROW; r++) {
        o[0] = w * acc[r][0];
        o[1] = w * acc[r][1];
        o[2] = w * acc[r][2];
        o += 4 * ROW_FLOATS;
    }
}

// ---------------------------------------------------------------------------
// Inputs (metadata order): x f32[128,224,224,3], kernels_table f32[32,32,32,3],
//                          amt i32[128], angles i32[128]
// ---------------------------------------------------------------------------
extern "C" void kernel_launch(void* const* d_in, const int* in_sizes, int n_in,
                              void* d_out, int out_size) {
    const float* x      = (const float*)d_in[0];
    const float* tbl    = (const float*)d_in[1];
    const int*   amt    = (const int*)d_in[2];
    const int*   angles = (const int*)d_in[3];
    float*       out    = (float*)d_out;

    static int smem_set = 0;
    const int smem_bytes = 256 + STOT * 8;         // 72832
    if (!smem_set) {
        cudaFuncSetAttribute(blur_fused_kernel,
                             cudaFuncAttributeMaxDynamicSharedMemorySize, smem_bytes);
        smem_set = 1;
    }

    build_taps_kernel<<<BATCH, KK * KK>>>(tbl, amt, angles);

    dim3 cgrid(HW / XB, HW / RB, BATCH);   // 2 x 7 x 128
    blur_fused_kernel<<<cgrid, NTHREADS, smem_bytes>>>(x, out);
}

// round 15
// speedup vs baseline: 1.7471x; 1.0339x over previous
#include <cuda_runtime.h>
#include <cuda_bf16.h>
#include <cuda_fp16.h>
#include <math.h>

#define BATCH 128
#define HW 224
#define CH 3
#define KK 32
#define PAD_LO 15                       // SAME pad for K=32: lo=15, hi=16
#define ROW_FLOATS (HW * CH)            // 672
#define ELEMS_PER_IMG (HW * HW * CH)    // 150528
#define MAX_TAPS 64

#define RB 32                           // output rows per block
#define XB 56                           // output cols per block
#define SROWS (RB + 31)                 // staged rows = 63
#define SPPX (XB + 32)                  // staged row width = 88 px
#define STOT (SROWS * SPPX)             // 5544 staged px
#define NTHREADS 448                    // 8 row-groups x 56 px
#define NROW 4                          // rows accumulated per thread (rg+8k)

__device__ int   g_cnt[BATCH];
__device__ float g_w[BATCH];            // uniform nonzero weight = 1/size
__device__ int   g_off[BATCH][MAX_TAPS];  // tap offset: dy*SPPX + dx (px units)

__device__ __forceinline__ unsigned h2_to_u32(__half2 h) {
    union { __half2 h; unsigned u; } cv; cv.h = h; return cv.u;
}
__device__ __forceinline__ __half2 u32_to_h2(unsigned u) {
    union { unsigned u; __half2 h; } cv; cv.u = u; return cv.h;
}

// ---------------------------------------------------------------------------
// Kernel 1: build rotated sparse tap list. One block per sample, one thread
// per kernel cell. Compaction order irrelevant (all nonzero weights equal).
// ---------------------------------------------------------------------------
__global__ void build_taps_kernel(const float* __restrict__ tbl,
                                  const int* __restrict__ amt,
                                  const int* __restrict__ angles) {
    const int b = blockIdx.x;
    const int tid = threadIdx.x;           // 0..1023
    const int yy = tid >> 5;
    const int xx = tid & 31;

    __shared__ int s_cnt;
    if (tid == 0) s_cnt = 0;
    __syncthreads();

    float rad = (float)angles[b] * 0.017453292519943295f;
    float c = cosf(rad);
    float s = sinf(rad);
    const float e = 31.0f;
    float x_off = (e - (c * e - s * e)) * 0.5f;
    float y_off = (e - (s * e + c * e)) * 0.5f;

    float sx = c * (float)xx - s * (float)yy + x_off;
    float sy = s * (float)xx + c * (float)yy + y_off;
    int ix = __float2int_rn(sx);           // round half to even == jnp.round
    int iy = __float2int_rn(sy);

    if (ix >= 0 && ix < KK && iy >= 0 && iy < KK) {
        // reference indexes kernels_table[amt] directly
        float w = tbl[((size_t)amt[b] * (KK * KK) + iy * KK + ix) * CH];
        if (w != 0.0f) {
            int dy = yy - PAD_LO;
            int dx = xx - PAD_LO;
            int k = atomicAdd(&s_cnt, 1);
            g_off[b][k] = dy * SPPX + dx;  // px-unit offset in staged tile
            g_w[b] = w;                    // all equal; benign race
        }
    }
    __syncthreads();
    if (tid == 0) g_cnt[b] = s_cnt;
}

// ---------------------------------------------------------------------------
// Kernel 2 (fused): stage halo'd fp16-RGBX window (63 x 88 px) in SMEM with
// batched loads, then sparse conv from SMEM.
// Block = 32 rows x 56 cols; thread = 1 px x 4 rows (rg, rg+8, rg+16, rg+24).
// 4 blocks co-resident per SM for deep stage/conv phase overlap.
// ---------------------------------------------------------------------------
__global__ void __launch_bounds__(NTHREADS, 4)
blur_fused_kernel(const float* __restrict__ in, float* __restrict__ out) {
    extern __shared__ char sm[];
    int*   s_off = (int*)sm;                       // 256 B
    uint2* tile  = (uint2*)(sm + 256);             // STOT*8 = 44352 B

    const int xb  = blockIdx.x * XB;
    const int yb  = blockIdx.y * RB;
    const int b   = blockIdx.z;
    const int tid = threadIdx.x;
    const int cnt = g_cnt[b];

    if (tid < cnt) s_off[tid] = g_off[b][tid];

    // ---- stage: batched loads (high MLP); 4 batches of 4 cover 7168 >= 5544 ----
    const float* img = in + (size_t)b * ELEMS_PER_IMG;
    #pragma unroll
    for (int batch = 0; batch < 4; batch++) {
        uint2 v[4];
        int   idx[4];
        #pragma unroll
        for (int k = 0; k < 4; k++) {
            int i = tid + (batch * 4 + k) * NTHREADS;
            idx[k] = i;
            v[k] = make_uint2(0u, 0u);
            if (i < STOT) {
                int row = i / SPPX;
                int px  = i - row * SPPX;
                int ys  = yb + row - 15;
                int xs  = xb + px - 16;
                if ((unsigned)ys < (unsigned)HW && (unsigned)xs < (unsigned)HW) {
                    const float* p = img + ys * ROW_FLOATS + xs * CH;
                    v[k].x = h2_to_u32(__floats2half2_rn(__ldg(p), __ldg(p + 1)));
                    v[k].y = h2_to_u32(__floats2half2_rn(__ldg(p + 2), 0.f));
                }
            }
        }
        #pragma unroll
        for (int k = 0; k < 4; k++)
            if (idx[k] < STOT) tile[idx[k]] = v[k];
    }
    __syncthreads();

    // ---- conv: thread = px x_local, rows yb+rg+{0,8,16,24} ----
    const int rg = tid / XB;               // 0..7
    const int xl = tid - rg * XB;          // 0..55

    const uint2* tp = tile + (15 + rg) * SPPX + (16 + xl);

    float a0 = 0.f, a1 = 0.f, a2 = 0.f;
    float b0 = 0.f, b1 = 0.f, b2 = 0.f;
    float c0 = 0.f, c1 = 0.f, c2 = 0.f;
    float d0 = 0.f, d1 = 0.f, d2 = 0.f;
    #pragma unroll 2
    for (int i = 0; i < cnt; i++) {
        int off = s_off[i];
        uint2 v0 = tp[off];
        uint2 v1 = tp[off +  8 * SPPX];
        uint2 v2 = tp[off + 16 * SPPX];
        uint2 v3 = tp[off + 24 * SPPX];
        float2 f0 = __half22float2(u32_to_h2(v0.x));
        float2 f1 = __half22float2(u32_to_h2(v1.x));
        float2 f2 = __half22float2(u32_to_h2(v2.x));
        float2 f3 = __half22float2(u32_to_h2(v3.x));
        a0 += f0.x; a1 += f0.y; a2 += __half2float(__low2half(u32_to_h2(v0.y)));
        b0 += f1.x; b1 += f1.y; b2 += __half2float(__low2half(u32_to_h2(v1.y)));
        c0 += f2.x; c1 += f2.y; c2 += __half2float(__low2half(u32_to_h2(v2.y)));
        d0 += f3.x; d1 += f3.y; d2 += __half2float(__low2half(u32_to_h2(v3.y)));
    }

    const float w = g_w[b];
    float* o = out + (size_t)b * ELEMS_PER_IMG
             + (size_t)(yb + rg) * ROW_FLOATS + (xb + xl) * CH;
    o[0] = w * a0;  o[1] = w * a1;  o[2] = w * a2;
    o += 8 * ROW_FLOATS;
    o[0] = w * b0;  o[1] = w * b1;  o[2] = w * b2;
    o += 8 * ROW_FLOATS;
    o[0] = w * c0;  o[1] = w * c1;  o[2] = w * c2;
    o += 8 * ROW_FLOATS;
    o[0] = w * d0;  o[1] = w * d1;  o[2] = w * d2;
}

// ---------------------------------------------------------------------------
// Inputs (metadata order): x f32[128,224,224,3], kernels_table f32[32,32,32,3],
//                          amt i32[128], angles i32[128]
// ---------------------------------------------------------------------------
extern "C" void kernel_launch(void* const* d_in, const int* in_sizes, int n_in,
                              void* d_out, int out_size) {
    const float* x      = (const float*)d_in[0];
    const float* tbl    = (const float*)d_in[1];
    const int*   amt    = (const int*)d_in[2];
    const int*   angles = (const int*)d_in[3];
    float*       out    = (float*)d_out;

    static int smem_set = 0;
    const int smem_bytes = 256 + STOT * 8;         // 44608
    if (!smem_set) {
        cudaFuncSetAttribute(blur_fused_kernel,
                             cudaFuncAttributeMaxDynamicSharedMemorySize, smem_bytes);
        smem_set = 1;
    }

    build_taps_kernel<<<BATCH, KK * KK>>>(tbl, amt, angles);

    dim3 cgrid(HW / XB, HW / RB, BATCH);   // 4 x 7 x 128
    blur_fused_kernel<<<cgrid, NTHREADS, smem_bytes>>>(x, out);
}